// round 12
// baseline (speedup 1.0000x reference)
#include <cuda_runtime.h>
#include <cstdint>

// ---------------------------------------------------------------------------
// Problem constants
// ---------------------------------------------------------------------------
#define DIM     512
#define OUTD    256
#define NN1     30000
#define NN2     15000
#define NN3     8000
#define NTOT    (NN1 + NN2 + NN3)
#define EMAXT   530000
#define EPS     1e-5f

// ---------------------------------------------------------------------------
// Static device scratch
// ---------------------------------------------------------------------------
__device__ float g_mean [NN1 * DIM];
__device__ float g_h    [NN1 * DIM];
__device__ float g_r    [NN1 * DIM];
__device__ float g_xr   [NN1 * DIM];      // tf32-rounded copy of x rows 0..NN1
__device__ float g_x1   [NN1 * DIM];
__device__ float g_x2   [NN2 * DIM];
__device__ float g_x3   [NN3 * DIM];
__device__ float g_z1   [NN3 * DIM];
__device__ float g_z2   [NN3 * OUTD];
__device__ float g_stats[3 * 2 * DIM];    // per-layer (sum, sumsq)
__device__ int   g_deg  [NTOT];
__device__ int   g_start[NTOT + 3];
__device__ int   g_cur  [NTOT];
__device__ int   g_adj  [EMAXT];
// transposed weights: 7x(512x512) + (512x2048) + (256x512)
#define WT_SEG  (512 * 512)
#define WT_W1   (7 * WT_SEG)
#define WT_W2   (WT_W1 + 2048 * 512)
__device__ float g_wt   [WT_W2 + 512 * 256];

// ---------------------------------------------------------------------------
// tf32 helpers (sm_80-level PTX, safe for plain sm_103 target)
// ---------------------------------------------------------------------------
__device__ __forceinline__ uint32_t f2tf32(float f) {
    uint32_t r;
    asm("cvt.rna.tf32.f32 %0, %1;" : "=r"(r) : "f"(f));
    return r;
}
__device__ __forceinline__ float roundtf(float f) {
    return __uint_as_float(f2tf32(f));
}

__device__ __forceinline__ void mma_tf32(float& d0, float& d1, float& d2, float& d3,
                                         uint32_t a0, uint32_t a1, uint32_t a2, uint32_t a3,
                                         uint32_t b0, uint32_t b1) {
    asm volatile(
        "mma.sync.aligned.m16n8k8.row.col.f32.tf32.tf32.f32 "
        "{%0,%1,%2,%3}, {%4,%5,%6,%7}, {%8,%9}, {%0,%1,%2,%3};"
        : "+f"(d0), "+f"(d1), "+f"(d2), "+f"(d3)
        : "r"(a0), "r"(a1), "r"(a2), "r"(a3), "r"(b0), "r"(b1));
}

__device__ __forceinline__ void cp_async16(uint32_t dst, const void* src, bool pred) {
    int sz = pred ? 16 : 0;
    asm volatile("cp.async.cg.shared.global [%0], [%1], 16, %2;"
                 :: "r"(dst), "l"(src), "r"(sz));
}
#define CP_COMMIT()  asm volatile("cp.async.commit_group;" ::: "memory")
#define CP_WAIT(n)   asm volatile("cp.async.wait_group %0;" :: "n"(n) : "memory")

#define LDMATRIX_X4(r0, r1, r2, r3, addr)                                      \
    asm volatile("ldmatrix.sync.aligned.m8n8.x4.shared.b16 {%0,%1,%2,%3}, [%4];" \
                 : "=r"(r0), "=r"(r1), "=r"(r2), "=r"(r3) : "r"(addr))

// ---------------------------------------------------------------------------
// Runtime-configurable tf32 mma.sync multi-segment GEMM (UNCHANGED from the
// 991us round-11 winner — do not touch).
// ---------------------------------------------------------------------------
#define SMS 20
#define BK  16

__global__ __launch_bounds__(256, 2)
void fused_gemm_kernel(const float* __restrict__ A0, const float* __restrict__ A1,
                       const float* __restrict__ A2, const float* __restrict__ A3,
                       const float* __restrict__ B0, const float* __restrict__ B1,
                       const float* __restrict__ B2, const float* __restrict__ B3,
                       int nseg, int ldB, const float* __restrict__ bias,
                       float* __restrict__ C, int ldC,
                       int M, int mainX, int doStats, float* statsBase, int roundOut,
                       const float* altA, const float* altB,
                       const float* altBias, float* altC) {
    __shared__ uint32_t As[2][128 * SMS];
    __shared__ uint32_t Bs[2][128 * SMS];

    const float* Aseg[4];
    const float* Bseg[4];
    int nsegL, ldBL, ldCL;
    const float* biasL;
    float* Cout;
    bool stats, doRound;
    int colBase;

    if ((int)blockIdx.x < mainX) {
        colBase = blockIdx.x * 128;
        Aseg[0] = A0; Aseg[1] = A1; Aseg[2] = A2; Aseg[3] = A3;
        Bseg[0] = B0; Bseg[1] = B1; Bseg[2] = B2; Bseg[3] = B3;
        nsegL = nseg; ldBL = ldB; biasL = bias; Cout = C; ldCL = ldC;
        stats = (doStats != 0);
        doRound = (roundOut != 0);
    } else {
        colBase = (blockIdx.x - mainX) * 128;
        Aseg[0] = altA; Aseg[1] = altA; Aseg[2] = altA; Aseg[3] = altA;
        Bseg[0] = altB; Bseg[1] = altB; Bseg[2] = altB; Bseg[3] = altB;
        nsegL = 1; ldBL = 512; biasL = altBias; Cout = altC; ldCL = 512;
        stats = false; doRound = false;
    }

    const int tid  = threadIdx.x;
    const int wid  = tid >> 5;
    const int lane = tid & 31;
    const int g    = lane >> 2;
    const int t    = lane & 3;

    const int rowBase = blockIdx.y * 128;
    const int warp_m  = (wid & 1) * 64;
    const int warp_n  = (wid >> 1) * 32;

    const int aRowQ = (lane & 7) + ((lane >> 3) & 1) * 8;
    const int aKq   = (lane >> 4) * 4;
    const int bRowQ = (lane & 7);
    const int bJsel = (lane >> 4) & 1;
    const int bKq   = ((lane >> 3) & 1) * 4;

    const int lr0 = tid >> 2, lc0 = (tid & 3) * 4;
    const int lr1 = lr0 + 64;

    uint32_t sA[2], sB[2];
    sA[0] = (uint32_t)__cvta_generic_to_shared(&As[0][0]);
    sA[1] = (uint32_t)__cvta_generic_to_shared(&As[1][0]);
    sB[0] = (uint32_t)__cvta_generic_to_shared(&Bs[0][0]);
    sB[1] = (uint32_t)__cvta_generic_to_shared(&Bs[1][0]);
    const uint32_t offA0 = (lr0 * SMS + lc0) * 4;
    const uint32_t offA1 = (lr1 * SMS + lc0) * 4;

    const int grow0 = rowBase + lr0;
    const int grow1 = rowBase + lr1;
    const int crow0 = grow0 < M ? grow0 : (M - 1);
    const int crow1 = grow1 < M ? grow1 : (M - 1);

    float acc[4][4][4];
#pragma unroll
    for (int i = 0; i < 4; i++)
#pragma unroll
        for (int j = 0; j < 4; j++)
#pragma unroll
            for (int k = 0; k < 4; k++) acc[i][j][k] = 0.f;

    const int nch = nsegL * (DIM / BK);   // always even

    auto load_chunk = [&](int c, uint32_t dstA, uint32_t dstB) {
        int seg = c >> 5;
        int kb  = (c & 31) * BK;
        const float* A = Aseg[seg];
        const float* B = Bseg[seg];
        cp_async16(dstA + offA0, A + (size_t)crow0 * DIM + kb + lc0, grow0 < M);
        cp_async16(dstA + offA1, A + (size_t)crow1 * DIM + kb + lc0, grow1 < M);
        cp_async16(dstB + offA0, B + (size_t)(colBase + lr0) * ldBL + kb + lc0, true);
        cp_async16(dstB + offA1, B + (size_t)(colBase + lr1) * ldBL + kb + lc0, true);
        CP_COMMIT();
    };

    auto compute = [&](uint32_t asb, uint32_t bsb) {
#pragma unroll
        for (int ks = 0; ks < 2; ks++) {
            int kof = ks * 8;
            uint32_t af[4][4];
#pragma unroll
            for (int i = 0; i < 4; i++) {
                uint32_t addr = asb + ((warp_m + i * 16 + aRowQ) * SMS + kof + aKq) * 4;
                LDMATRIX_X4(af[i][0], af[i][1], af[i][2], af[i][3], addr);
            }
            uint32_t bf[4][2];
#pragma unroll
            for (int jp = 0; jp < 2; jp++) {
                uint32_t addr = bsb + ((warp_n + (jp * 2 + bJsel) * 8 + bRowQ) * SMS + kof + bKq) * 4;
                LDMATRIX_X4(bf[jp * 2][0], bf[jp * 2][1], bf[jp * 2 + 1][0], bf[jp * 2 + 1][1], addr);
            }
#pragma unroll
            for (int j = 0; j < 4; j++)
#pragma unroll
                for (int i = 0; i < 4; i++)
                    mma_tf32(acc[i][j][0], acc[i][j][1], acc[i][j][2], acc[i][j][3],
                             af[i][0], af[i][1], af[i][2], af[i][3],
                             bf[j][0], bf[j][1]);
        }
    };

    load_chunk(0, sA[0], sB[0]);

    for (int c = 0; c < nch; c += 2) {
        load_chunk(c + 1, sA[1], sB[1]);
        CP_WAIT(1);
        __syncthreads();
        compute(sA[0], sB[0]);
        __syncthreads();

        if (c + 2 < nch) { load_chunk(c + 2, sA[0], sB[0]); CP_WAIT(1); }
        else             { CP_WAIT(0); }
        __syncthreads();
        compute(sA[1], sB[1]);
        __syncthreads();
    }

#pragma unroll
    for (int j = 0; j < 4; j++) {
        int col = colBase + warp_n + j * 8 + 2 * t;
        float bx = 0.f, by = 0.f;
        if (biasL) { bx = biasL[col]; by = biasL[col + 1]; }

        float s0 = 0.f, s1 = 0.f, q0 = 0.f, q1 = 0.f;
#pragma unroll
        for (int i = 0; i < 4; i++) {
            int row0 = rowBase + warp_m + i * 16 + g;
            if (row0 < M) {
                float v0 = acc[i][j][0] + bx;
                float v1 = acc[i][j][1] + by;
                s0 += v0; q0 = fmaf(v0, v0, q0);
                s1 += v1; q1 = fmaf(v1, v1, q1);
                if (doRound) { v0 = roundtf(v0); v1 = roundtf(v1); }
                *reinterpret_cast<float2*>(Cout + (size_t)row0 * ldCL + col) =
                    make_float2(v0, v1);
            }
            if (row0 + 8 < M) {
                float v2 = acc[i][j][2] + bx;
                float v3 = acc[i][j][3] + by;
                s0 += v2; q0 = fmaf(v2, v2, q0);
                s1 += v3; q1 = fmaf(v3, v3, q1);
                if (doRound) { v2 = roundtf(v2); v3 = roundtf(v3); }
                *reinterpret_cast<float2*>(Cout + (size_t)(row0 + 8) * ldCL + col) =
                    make_float2(v2, v3);
            }
        }
        if (stats) {
#pragma unroll
            for (int o = 4; o <= 16; o <<= 1) {
                s0 += __shfl_xor_sync(0xffffffffu, s0, o);
                s1 += __shfl_xor_sync(0xffffffffu, s1, o);
                q0 += __shfl_xor_sync(0xffffffffu, q0, o);
                q1 += __shfl_xor_sync(0xffffffffu, q1, o);
            }
            if (g == 0) {
                atomicAdd(&statsBase[col],           s0);
                atomicAdd(&statsBase[col + 1],       s1);
                atomicAdd(&statsBase[DIM + col],     q0);
                atomicAdd(&statsBase[DIM + col + 1], q1);
            }
        }
    }
}

// ---------------------------------------------------------------------------
// Combined 3-layer CSR build
// ---------------------------------------------------------------------------
__global__ void zero_all_kernel(int* __restrict__ deg, float* __restrict__ stats) {
    int i = blockIdx.x * blockDim.x + threadIdx.x;
    if (i < NTOT) deg[i] = 0;
    if (i < 3 * 2 * DIM) stats[i] = 0.f;
}

__global__ void count3_kernel(const int* __restrict__ ei1, const int* __restrict__ ei2,
                              const int* __restrict__ ei3, int E1, int E2, int E3,
                              int* __restrict__ deg) {
    int i = blockIdx.x * blockDim.x + threadIdx.x;
    const int* dst; int idx, off;
    if (i < E1)                { dst = ei1 + E1; idx = i;            off = 0; }
    else if (i < E1 + E2)      { dst = ei2 + E2; idx = i - E1;       off = NN1; }
    else if (i < E1 + E2 + E3) { dst = ei3 + E3; idx = i - E1 - E2;  off = NN1 + NN2; }
    else return;
    atomicAdd(&deg[off + dst[idx]], 1);
}

__global__ void scan3_kernel(const int* __restrict__ deg, int* __restrict__ start,
                             int* __restrict__ cursor) {
    __shared__ int sh[1024];
    __shared__ int carry;
    int t = threadIdx.x;
    const int Ms[3]     = {NN1, NN2, NN3};
    const int degoff[3] = {0, NN1, NN1 + NN2};
    const int stoff[3]  = {0, NN1 + 1, NN1 + NN2 + 2};
    for (int seg = 0; seg < 3; seg++) {
        int M = Ms[seg];
        if (t == 0) carry = 0;
        __syncthreads();
        for (int base = 0; base < M; base += 1024) {
            int i = base + t;
            int v = (i < M) ? deg[degoff[seg] + i] : 0;
            sh[t] = v;
            __syncthreads();
            for (int off = 1; off < 1024; off <<= 1) {
                int u = (t >= off) ? sh[t - off] : 0;
                __syncthreads();
                sh[t] += u;
                __syncthreads();
            }
            if (i < M) {
                start[stoff[seg] + i] = carry + sh[t] - v;
                cursor[degoff[seg] + i] = 0;
            }
            __syncthreads();
            if (t == 1023) carry += sh[1023];
            __syncthreads();
        }
        if (t == 0) start[stoff[seg] + M] = carry;
        __syncthreads();
    }
}

__global__ void fill3_kernel(const int* __restrict__ ei1, const int* __restrict__ ei2,
                             const int* __restrict__ ei3, int E1, int E2, int E3,
                             const int* __restrict__ start, int* __restrict__ cursor,
                             int* __restrict__ adj) {
    int i = blockIdx.x * blockDim.x + threadIdx.x;
    const int* src; const int* dst; int idx, noff, soff, aoff;
    if (i < E1)                { src = ei1; dst = ei1 + E1; idx = i;           noff = 0;         soff = 0;             aoff = 0; }
    else if (i < E1 + E2)      { src = ei2; dst = ei2 + E2; idx = i - E1;      noff = NN1;       soff = NN1 + 1;       aoff = E1; }
    else if (i < E1 + E2 + E3) { src = ei3; dst = ei3 + E3; idx = i - E1 - E2; noff = NN1 + NN2; soff = NN1 + NN2 + 2; aoff = E1 + E2; }
    else return;
    int d = dst[idx];
    int p = atomicAdd(&cursor[noff + d], 1);
    adj[aoff + start[soff + d] + p] = src[idx];
}

// ---------------------------------------------------------------------------
// gather-mean: 256 threads/block; neighbor list split across two thread-halves
// (halves the per-row serial accumulation chain), smem-combined. Output
// rounded to tf32 RNA.
// ---------------------------------------------------------------------------
__global__ void gather_mean_kernel(const float* __restrict__ x,
                                   const int* __restrict__ adj,
                                   const int* __restrict__ start,
                                   float* __restrict__ mean, int M) {
    __shared__ float4 part[128];
    int d = blockIdx.x;
    if (d >= M) return;
    int t = threadIdx.x;          // 0..255
    int h = t >> 7;               // half 0 / 1
    int l = t & 127;              // float4 lane
    int s0 = start[d], s1 = start[d + 1];

    float4 a0 = make_float4(0.f, 0.f, 0.f, 0.f);
    float4 a1 = make_float4(0.f, 0.f, 0.f, 0.f);
    int j = s0 + h;
    for (; j + 2 < s1; j += 4) {      // this half handles j and j+2
        int nA = adj[j], nB = adj[j + 2];
        float4 vA = reinterpret_cast<const float4*>(x + (size_t)nA * DIM)[l];
        float4 vB = reinterpret_cast<const float4*>(x + (size_t)nB * DIM)[l];
        a0.x += vA.x; a0.y += vA.y; a0.z += vA.z; a0.w += vA.w;
        a1.x += vB.x; a1.y += vB.y; a1.z += vB.z; a1.w += vB.w;
    }
    if (j < s1) {
        int nA = adj[j];
        float4 vA = reinterpret_cast<const float4*>(x + (size_t)nA * DIM)[l];
        a0.x += vA.x; a0.y += vA.y; a0.z += vA.z; a0.w += vA.w;
    }
    a0.x += a1.x; a0.y += a1.y; a0.z += a1.z; a0.w += a1.w;

    if (h == 1) part[l] = a0;
    __syncthreads();
    if (h == 0) {
        float4 p = part[l];
        int deg = s1 - s0;
        float inv = 1.f / (float)(deg > 1 ? deg : 1);
        float4 r;
        r.x = roundtf((a0.x + p.x) * inv);
        r.y = roundtf((a0.y + p.y) * inv);
        r.z = roundtf((a0.z + p.z) * inv);
        r.w = roundtf((a0.w + p.w) * inv);
        reinterpret_cast<float4*>(mean + (size_t)d * DIM)[l] = r;
    }
}

// ---------------------------------------------------------------------------
// Weight transpose (output rounded to tf32 RNA): [K,N] -> [N,K]
// ---------------------------------------------------------------------------
struct TPtrs { const float* in[7]; float* out[7]; };

__global__ void transpose7_kernel(TPtrs p) {
    __shared__ float t[32][33];
    const float* in = p.in[blockIdx.z];
    float* out = p.out[blockIdx.z];
    int kb = blockIdx.y * 32, nb = blockIdx.x * 32;
    int tx = threadIdx.x, ty = threadIdx.y;
#pragma unroll
    for (int i = 0; i < 32; i += 8)
        t[ty + i][tx] = in[(size_t)(kb + ty + i) * 512 + nb + tx];
    __syncthreads();
#pragma unroll
    for (int i = 0; i < 32; i += 8)
        out[(size_t)(nb + ty + i) * 512 + kb + tx] = roundtf(t[tx][ty + i]);
}

__global__ void transpose_kernel(const float* __restrict__ in, float* __restrict__ out,
                                 int K, int N) {
    __shared__ float t[32][33];
    int kb = blockIdx.y * 32, nb = blockIdx.x * 32;
    int tx = threadIdx.x, ty = threadIdx.y;
#pragma unroll
    for (int i = 0; i < 32; i += 8)
        t[ty + i][tx] = in[(size_t)(kb + ty + i) * N + nb + tx];
    __syncthreads();
#pragma unroll
    for (int i = 0; i < 32; i += 8)
        out[(size_t)(nb + ty + i) * K + kb + tx] = roundtf(t[tx][ty + i]);
}

// rounded copy: x -> xr (tf32 RNA)
__global__ void round_copy_kernel(const float* __restrict__ in, float* __restrict__ out, int n4) {
    int i = blockIdx.x * blockDim.x + threadIdx.x;
    if (i < n4) {
        float4 v = reinterpret_cast<const float4*>(in)[i];
        v.x = roundtf(v.x); v.y = roundtf(v.y); v.z = roundtf(v.z); v.w = roundtf(v.w);
        reinterpret_cast<float4*>(out)[i] = v;
    }
}

// ---------------------------------------------------------------------------
// Epilogue with INLINE finalize: each block derives the BN affine coeffs from
// g_stats into smem, then grid-strides over rows.
// x_out = round_tf32(leaky(bn(h)) + res)
// ---------------------------------------------------------------------------
__global__ void epilogue_kernel(const float* __restrict__ h, const float* __restrict__ res,
                                float* __restrict__ xout, int M,
                                const float* __restrict__ gg, const float* __restrict__ bb,
                                const float* __restrict__ statsBase) {
    __shared__ float sab[2 * DIM];
    int t = threadIdx.x;              // 256
    float inv_m = 1.f / (float)M;
#pragma unroll
    for (int f = t; f < DIM; f += 256) {
        float mu  = statsBase[f] * inv_m;
        float var = statsBase[DIM + f] * inv_m - mu * mu;
        float rstd = rsqrtf(var + EPS);
        float a = gg[f] * rstd;
        sab[f] = a;
        sab[DIM + f] = bb[f] - mu * a;
    }
    __syncthreads();

    int total = M * (DIM / 4);
    for (int i = blockIdx.x * 256 + t; i < total; i += gridDim.x * 256) {
        int f4 = (i & 127) * 4;
        float4 hv = reinterpret_cast<const float4*>(h)[i];
        float4 rv = reinterpret_cast<const float4*>(res)[i];
        float4 o;
        float v;
        v = fmaf(hv.x, sab[f4 + 0], sab[DIM + f4 + 0]); v = v > 0.f ? v : 0.01f * v; o.x = roundtf(v + rv.x);
        v = fmaf(hv.y, sab[f4 + 1], sab[DIM + f4 + 1]); v = v > 0.f ? v : 0.01f * v; o.y = roundtf(v + rv.y);
        v = fmaf(hv.z, sab[f4 + 2], sab[DIM + f4 + 2]); v = v > 0.f ? v : 0.01f * v; o.z = roundtf(v + rv.z);
        v = fmaf(hv.w, sab[f4 + 3], sab[DIM + f4 + 3]); v = v > 0.f ? v : 0.01f * v; o.w = roundtf(v + rv.w);
        reinterpret_cast<float4*>(xout)[i] = o;
    }
}

__global__ void lsm_kernel(const float* __restrict__ z, float* __restrict__ out) {
    int row = blockIdx.x;
    int t = threadIdx.x;
    float v = z[(size_t)row * OUTD + t];
    __shared__ float sh[8];
    float m = v;
#pragma unroll
    for (int o = 16; o; o >>= 1) m = fmaxf(m, __shfl_xor_sync(0xffffffffu, m, o));
    if ((t & 31) == 0) sh[t >> 5] = m;
    __syncthreads();
    if (t == 0) {
        float mm = sh[0];
#pragma unroll
        for (int i = 1; i < 8; i++) mm = fmaxf(mm, sh[i]);
        sh[0] = mm;
    }
    __syncthreads();
    float mx = sh[0];
    __syncthreads();
    float e = expf(v - mx);
    float s = e;
#pragma unroll
    for (int o = 16; o; o >>= 1) s += __shfl_xor_sync(0xffffffffu, s, o);
    if ((t & 31) == 0) sh[t >> 5] = s;
    __syncthreads();
    if (t == 0) {
        float ss = 0.f;
#pragma unroll
        for (int i = 0; i < 8; i++) ss += sh[i];
        sh[0] = ss;
    }
    __syncthreads();
    out[(size_t)row * OUTD + t] = v - mx - logf(sh[0]);
}

// ---------------------------------------------------------------------------
// Host orchestration
// ---------------------------------------------------------------------------
static inline int ceil_div(int a, int b) { return (a + b - 1) / b; }

extern "C" void kernel_launch(void* const* d_in, const int* in_sizes, int n_in,
                              void* d_out, int out_size) {
    const float* x      = (const float*)d_in[0];
    const int*   ei1    = (const int*)  d_in[1];
    const int*   ei2    = (const int*)  d_in[2];
    const int*   ei3    = (const int*)  d_in[3];
    const float* Wl1    = (const float*)d_in[4];
    const float* Wr1    = (const float*)d_in[5];
    const float* g1     = (const float*)d_in[6];
    const float* b1     = (const float*)d_in[7];
    const float* Wl2    = (const float*)d_in[8];
    const float* Wr2    = (const float*)d_in[9];
    const float* g2     = (const float*)d_in[10];
    const float* b2     = (const float*)d_in[11];
    const float* Wl3    = (const float*)d_in[12];
    const float* Wr3    = (const float*)d_in[13];
    const float* g3     = (const float*)d_in[14];
    const float* b3     = (const float*)d_in[15];
    const float* res_W  = (const float*)d_in[16];
    const float* res_b  = (const float*)d_in[17];
    const float* mlp_W1 = (const float*)d_in[18];
    const float* mlp_b1 = (const float*)d_in[19];
    const float* mlp_W2 = (const float*)d_in[20];
    const float* mlp_b2 = (const float*)d_in[21];
    float* out = (float*)d_out;

    int E1 = in_sizes[1] / 2;
    int E2 = in_sizes[2] / 2;
    int E3 = in_sizes[3] / 2;
    int ET = E1 + E2 + E3;

    float *p_mean, *p_h, *p_r, *p_xr, *p_x1, *p_x2, *p_x3, *p_z1, *p_z2, *p_stats, *p_wt;
    int *p_deg, *p_start, *p_cur, *p_adj;
    cudaGetSymbolAddress((void**)&p_mean,  g_mean);
    cudaGetSymbolAddress((void**)&p_h,     g_h);
    cudaGetSymbolAddress((void**)&p_r,     g_r);
    cudaGetSymbolAddress((void**)&p_xr,    g_xr);
    cudaGetSymbolAddress((void**)&p_x1,    g_x1);
    cudaGetSymbolAddress((void**)&p_x2,    g_x2);
    cudaGetSymbolAddress((void**)&p_x3,    g_x3);
    cudaGetSymbolAddress((void**)&p_z1,    g_z1);
    cudaGetSymbolAddress((void**)&p_z2,    g_z2);
    cudaGetSymbolAddress((void**)&p_stats, g_stats);
    cudaGetSymbolAddress((void**)&p_wt,    g_wt);
    cudaGetSymbolAddress((void**)&p_deg,   g_deg);
    cudaGetSymbolAddress((void**)&p_start, g_start);
    cudaGetSymbolAddress((void**)&p_cur,   g_cur);
    cudaGetSymbolAddress((void**)&p_adj,   g_adj);

    // --- combined CSR build + stats zero ---
    zero_all_kernel<<<ceil_div(NTOT, 256), 256>>>(p_deg, p_stats);
    count3_kernel<<<ceil_div(ET, 256), 256>>>(ei1, ei2, ei3, E1, E2, E3, p_deg);
    scan3_kernel<<<1, 1024>>>(p_deg, p_start, p_cur);
    fill3_kernel<<<ceil_div(ET, 256), 256>>>(ei1, ei2, ei3, E1, E2, E3,
                                             p_start, p_cur, p_adj);

    // --- transpose all weights to K-major [N, K], rounded to tf32 ---
    float* wt_Wl1 = p_wt + 0 * WT_SEG;
    float* wt_Wr1 = p_wt + 1 * WT_SEG;
    float* wt_Wl2 = p_wt + 2 * WT_SEG;
    float* wt_Wr2 = p_wt + 3 * WT_SEG;
    float* wt_Wl3 = p_wt + 4 * WT_SEG;
    float* wt_Wr3 = p_wt + 5 * WT_SEG;
    float* wt_res = p_wt + 6 * WT_SEG;
    float* wt_W1  = p_wt + WT_W1;
    float* wt_W2  = p_wt + WT_W2;
    {
        dim3 blk(32, 8);
        TPtrs tp;
        tp.in[0] = Wl1;  tp.out[0] = wt_Wl1;
        tp.in[1] = Wr1;  tp.out[1] = wt_Wr1;
        tp.in[2] = Wl2;  tp.out[2] = wt_Wl2;
        tp.in[3] = Wr2;  tp.out[3] = wt_Wr2;
        tp.in[4] = Wl3;  tp.out[4] = wt_Wl3;
        tp.in[5] = Wr3;  tp.out[5] = wt_Wr3;
        tp.in[6] = res_W; tp.out[6] = wt_res;
        transpose7_kernel<<<dim3(16, 16, 7), blk>>>(tp);
        transpose_kernel<<<dim3(16, 64), blk>>>(mlp_W1, wt_W1, 2048, 512);
        transpose_kernel<<<dim3(8,  16), blk>>>(mlp_W2, wt_W2, 512, 256);
    }

    // rounded copy of x rows 0..NN1 (GEMM A operand for layer 1 + MLP)
    round_copy_kernel<<<ceil_div(NN1 * (DIM / 4), 256), 256>>>(x, p_xr, NN1 * (DIM / 4));

    struct Layer {
        int M;
        const float* x_gather;
        const float* x_gemm;
        const int* startL; const int* adjL;
        const float* Wlt; const float* Wrt; const float* g; const float* b;
        float* x_out;
    };
    Layer layers[3] = {
        { NN1, x,    p_xr, p_start,                 p_adj,           wt_Wl1, wt_Wr1, g1, b1, p_x1 },
        { NN2, p_x1, p_x1, p_start + NN1 + 1,       p_adj + E1,      wt_Wl2, wt_Wr2, g2, b2, p_x2 },
        { NN3, p_x2, p_x2, p_start + NN1 + NN2 + 2, p_adj + E1 + E2, wt_Wl3, wt_Wr3, g3, b3, p_x3 },
    };

    for (int L = 0; L < 3; L++) {
        Layer& ly = layers[L];
        int M = ly.M;
        float* statsL = p_stats + L * 2 * DIM;

        gather_mean_kernel<<<M, 256>>>(ly.x_gather, ly.adjL, ly.startL, p_mean, M);

        // h = mean @ Wl + x_dst @ Wr (stats fused); L0 also r = x @ res_W + res_b
        {
            int mainX = DIM / 128;
            int altX  = (L == 0) ? (DIM / 128) : 0;
            dim3 grid(mainX + altX, ceil_div(M, 128));
            fused_gemm_kernel<<<grid, 256>>>(
                p_mean, ly.x_gemm, nullptr, nullptr,
                ly.Wlt, ly.Wrt, nullptr, nullptr,
                2, 512, nullptr, p_h, DIM,
                M, mainX, 1, statsL, 0,
                (L == 0) ? ly.x_gemm : nullptr,
                (L == 0) ? wt_res : nullptr,
                (L == 0) ? res_b : nullptr,
                (L == 0) ? p_r : nullptr);
        }

        // epilogue with inline finalize (grid-stride)
        const float* res = (L == 0) ? p_r : ly.x_gemm;
        epilogue_kernel<<<592, 256>>>(p_h, res, ly.x_out, M, ly.g, ly.b, statsL);
    }

    // MLP head: feat = [x | x1 | x2 | x3][:8000] (implicit concat); round z1
    {
        dim3 grid(DIM / 128, ceil_div(NN3, 128));
        fused_gemm_kernel<<<grid, 256>>>(
            p_xr, p_x1, p_x2, p_x3,
            wt_W1, wt_W1 + 512, wt_W1 + 1024, wt_W1 + 1536,
            4, 2048, mlp_b1, p_z1, DIM,
            NN3, DIM / 128, 0, nullptr, 1,
            nullptr, nullptr, nullptr, nullptr);
    }
    {
        dim3 grid(OUTD / 128, ceil_div(NN3, 128));
        fused_gemm_kernel<<<grid, 256>>>(
            p_z1, nullptr, nullptr, nullptr,
            wt_W2, nullptr, nullptr, nullptr,
            1, 512, mlp_b2, p_z2, OUTD,
            NN3, OUTD / 128, 0, nullptr, 0,
            nullptr, nullptr, nullptr, nullptr);
    }

    lsm_kernel<<<NN3, OUTD>>>(p_z2, out);
}

// round 13
// speedup vs baseline: 1.0688x; 1.0688x over previous
#include <cuda_runtime.h>
#include <cstdint>

// ---------------------------------------------------------------------------
// Problem constants
// ---------------------------------------------------------------------------
#define DIM     512
#define OUTD    256
#define NN1     30000
#define NN2     15000
#define NN3     8000
#define NTOT    (NN1 + NN2 + NN3)
#define EMAXT   530000
#define EPS     1e-5f

// ---------------------------------------------------------------------------
// Static device scratch
// ---------------------------------------------------------------------------
__device__ float g_mean [NN1 * DIM];
__device__ float g_h    [NN1 * DIM];
__device__ float g_r    [NN1 * DIM];
__device__ float g_xr   [NN1 * DIM];      // tf32-rounded copy of x rows 0..NN1
__device__ float g_x1   [NN1 * DIM];
__device__ float g_x2   [NN2 * DIM];
__device__ float g_x3   [NN3 * DIM];
__device__ float g_z1   [NN3 * DIM];
__device__ float g_z2   [NN3 * OUTD];
__device__ float g_stats[3 * 2 * DIM];    // per-layer (sum, sumsq)
__device__ float g_ab   [2 * DIM];
__device__ int   g_deg  [NTOT];
__device__ int   g_start[NTOT + 3];
__device__ int   g_cur  [NTOT];
__device__ int   g_adj  [EMAXT];
// transposed weights: 7x(512x512) + (512x2048) + (256x512)
#define WT_SEG  (512 * 512)
#define WT_W1   (7 * WT_SEG)
#define WT_W2   (WT_W1 + 2048 * 512)
__device__ float g_wt   [WT_W2 + 512 * 256];

// ---------------------------------------------------------------------------
// tf32 helpers (sm_80-level PTX, safe for plain sm_103 target)
// ---------------------------------------------------------------------------
__device__ __forceinline__ uint32_t f2tf32(float f) {
    uint32_t r;
    asm("cvt.rna.tf32.f32 %0, %1;" : "=r"(r) : "f"(f));
    return r;
}
__device__ __forceinline__ float roundtf(float f) {
    return __uint_as_float(f2tf32(f));
}

__device__ __forceinline__ void mma_tf32(float& d0, float& d1, float& d2, float& d3,
                                         uint32_t a0, uint32_t a1, uint32_t a2, uint32_t a3,
                                         uint32_t b0, uint32_t b1) {
    asm volatile(
        "mma.sync.aligned.m16n8k8.row.col.f32.tf32.tf32.f32 "
        "{%0,%1,%2,%3}, {%4,%5,%6,%7}, {%8,%9}, {%0,%1,%2,%3};"
        : "+f"(d0), "+f"(d1), "+f"(d2), "+f"(d3)
        : "r"(a0), "r"(a1), "r"(a2), "r"(a3), "r"(b0), "r"(b1));
}

__device__ __forceinline__ void cp_async16(uint32_t dst, const void* src, bool pred) {
    int sz = pred ? 16 : 0;
    asm volatile("cp.async.cg.shared.global [%0], [%1], 16, %2;"
                 :: "r"(dst), "l"(src), "r"(sz));
}
#define CP_COMMIT()  asm volatile("cp.async.commit_group;" ::: "memory")
#define CP_WAIT(n)   asm volatile("cp.async.wait_group %0;" :: "n"(n) : "memory")

#define LDMATRIX_X4(r0, r1, r2, r3, addr)                                      \
    asm volatile("ldmatrix.sync.aligned.m8n8.x4.shared.b16 {%0,%1,%2,%3}, [%4];" \
                 : "=r"(r0), "=r"(r1), "=r"(r2), "=r"(r3) : "r"(addr))

// ---------------------------------------------------------------------------
// Runtime-configurable tf32 mma.sync multi-segment GEMM.
// ALL A/B operands must be pre-rounded to tf32 (RNA).
// 4-STAGE cp.async pipeline, ONE __syncthreads per chunk, unrolled x4 so all
// buffer indices are compile-time literals (no runtime-indexed state!).
// BM=128, BN=128, BK=16, 256 threads = 8 warps (64x32 warp tile).
// ---------------------------------------------------------------------------
#define SMS 20
#define BK  16
#define TILE_BYTES  (128 * SMS * 4)        // 10240
#define STAGE_BYTES (2 * TILE_BYTES)       // 20480 (A + B)
#define GEMM_SMEM   (4 * STAGE_BYTES)      // 81920

__global__ __launch_bounds__(256, 2)
void fused_gemm_kernel(const float* __restrict__ A0, const float* __restrict__ A1,
                       const float* __restrict__ A2, const float* __restrict__ A3,
                       const float* __restrict__ B0, const float* __restrict__ B1,
                       const float* __restrict__ B2, const float* __restrict__ B3,
                       int nseg, int ldB, const float* __restrict__ bias,
                       float* __restrict__ C, int ldC,
                       int M, int mainX, int doStats, float* statsBase, int roundOut,
                       const float* altA, const float* altB,
                       const float* altBias, float* altC) {
    extern __shared__ uint32_t dynsmem[];

    const float* Aseg[4];
    const float* Bseg[4];
    int nsegL, ldBL, ldCL;
    const float* biasL;
    float* Cout;
    bool stats, doRound;
    int colBase;

    if ((int)blockIdx.x < mainX) {
        colBase = blockIdx.x * 128;
        Aseg[0] = A0; Aseg[1] = A1; Aseg[2] = A2; Aseg[3] = A3;
        Bseg[0] = B0; Bseg[1] = B1; Bseg[2] = B2; Bseg[3] = B3;
        nsegL = nseg; ldBL = ldB; biasL = bias; Cout = C; ldCL = ldC;
        stats = (doStats != 0);
        doRound = (roundOut != 0);
    } else {
        colBase = (blockIdx.x - mainX) * 128;
        Aseg[0] = altA; Aseg[1] = altA; Aseg[2] = altA; Aseg[3] = altA;
        Bseg[0] = altB; Bseg[1] = altB; Bseg[2] = altB; Bseg[3] = altB;
        nsegL = 1; ldBL = 512; biasL = altBias; Cout = altC; ldCL = 512;
        stats = false; doRound = false;
    }

    const int tid  = threadIdx.x;
    const int wid  = tid >> 5;
    const int lane = tid & 31;
    const int g    = lane >> 2;
    const int t    = lane & 3;

    const int rowBase = blockIdx.y * 128;
    const int warp_m  = (wid & 1) * 64;
    const int warp_n  = (wid >> 1) * 32;

    const int aRowQ = (lane & 7) + ((lane >> 3) & 1) * 8;
    const int aKq   = (lane >> 4) * 4;
    const int bRowQ = (lane & 7);
    const int bJsel = (lane >> 4) & 1;
    const int bKq   = ((lane >> 3) & 1) * 4;

    const int lr0 = tid >> 2, lc0 = (tid & 3) * 4;
    const int lr1 = lr0 + 64;

    const uint32_t smbase = (uint32_t)__cvta_generic_to_shared(dynsmem);
    const uint32_t offA0 = (lr0 * SMS + lc0) * 4;
    const uint32_t offA1 = (lr1 * SMS + lc0) * 4;

    const int grow0 = rowBase + lr0;
    const int grow1 = rowBase + lr1;
    const int crow0 = grow0 < M ? grow0 : (M - 1);
    const int crow1 = grow1 < M ? grow1 : (M - 1);

    float acc[4][4][4];
#pragma unroll
    for (int i = 0; i < 4; i++)
#pragma unroll
        for (int j = 0; j < 4; j++)
#pragma unroll
            for (int k = 0; k < 4; k++) acc[i][j][k] = 0.f;

    const int nch = nsegL * (DIM / BK);   // 32/64/128 — divisible by 4

    auto load_chunk = [&](int c, uint32_t dstA, uint32_t dstB) {
        int seg = c >> 5;
        int kb  = (c & 31) * BK;
        const float* A = Aseg[seg];
        const float* B = Bseg[seg];
        cp_async16(dstA + offA0, A + (size_t)crow0 * DIM + kb + lc0, grow0 < M);
        cp_async16(dstA + offA1, A + (size_t)crow1 * DIM + kb + lc0, grow1 < M);
        cp_async16(dstB + offA0, B + (size_t)(colBase + lr0) * ldBL + kb + lc0, true);
        cp_async16(dstB + offA1, B + (size_t)(colBase + lr1) * ldBL + kb + lc0, true);
        CP_COMMIT();
    };

    auto compute = [&](uint32_t asb, uint32_t bsb) {
#pragma unroll
        for (int ks = 0; ks < 2; ks++) {
            int kof = ks * 8;
            uint32_t af[4][4];
#pragma unroll
            for (int i = 0; i < 4; i++) {
                uint32_t addr = asb + ((warp_m + i * 16 + aRowQ) * SMS + kof + aKq) * 4;
                LDMATRIX_X4(af[i][0], af[i][1], af[i][2], af[i][3], addr);
            }
            uint32_t bf[4][2];
#pragma unroll
            for (int jp = 0; jp < 2; jp++) {
                uint32_t addr = bsb + ((warp_n + (jp * 2 + bJsel) * 8 + bRowQ) * SMS + kof + bKq) * 4;
                LDMATRIX_X4(bf[jp * 2][0], bf[jp * 2][1], bf[jp * 2 + 1][0], bf[jp * 2 + 1][1], addr);
            }
#pragma unroll
            for (int j = 0; j < 4; j++)
#pragma unroll
                for (int i = 0; i < 4; i++)
                    mma_tf32(acc[i][j][0], acc[i][j][1], acc[i][j][2], acc[i][j][3],
                             af[i][0], af[i][1], af[i][2], af[i][3],
                             bf[j][0], bf[j][1]);
        }
    };

    // stage s: A at s*STAGE_BYTES, B at s*STAGE_BYTES + TILE_BYTES (literals)
#define SA(s) (smbase + (s) * STAGE_BYTES)
#define SB(s) (smbase + (s) * STAGE_BYTES + TILE_BYTES)

    // prologue: fill stages 0,1,2 (nch >= 32)
    load_chunk(0, SA(0), SB(0));
    load_chunk(1, SA(1), SB(1));
    load_chunk(2, SA(2), SB(2));

    // One step per chunk cc: wait(2) completes group cc (groups 0..cc+2
    // committed so far); barrier gives cross-thread visibility AND protects
    // the load target (computed at iter cc-1); then load chunk cc+3 (or an
    // empty commit to keep group counting uniform); then compute chunk cc.
#define STEP(cc, CB, LB) do {                                                  \
        CP_WAIT(2);                                                            \
        __syncthreads();                                                       \
        if ((cc) + 3 < nch) load_chunk((cc) + 3, SA(LB), SB(LB));              \
        else                CP_COMMIT();                                       \
        compute(SA(CB), SB(CB));                                               \
    } while (0)

    for (int c = 0; c < nch; c += 4) {
        STEP(c + 0, 0, 3);
        STEP(c + 1, 1, 0);
        STEP(c + 2, 2, 1);
        STEP(c + 3, 3, 2);
    }
    CP_WAIT(0);
#undef STEP
#undef SA
#undef SB

    // ------------- epilogue: store + optional fused column stats -------------
#pragma unroll
    for (int j = 0; j < 4; j++) {
        int col = colBase + warp_n + j * 8 + 2 * t;
        float bx = 0.f, by = 0.f;
        if (biasL) { bx = biasL[col]; by = biasL[col + 1]; }

        float s0 = 0.f, s1 = 0.f, q0 = 0.f, q1 = 0.f;
#pragma unroll
        for (int i = 0; i < 4; i++) {
            int row0 = rowBase + warp_m + i * 16 + g;
            if (row0 < M) {
                float v0 = acc[i][j][0] + bx;
                float v1 = acc[i][j][1] + by;
                s0 += v0; q0 = fmaf(v0, v0, q0);
                s1 += v1; q1 = fmaf(v1, v1, q1);
                if (doRound) { v0 = roundtf(v0); v1 = roundtf(v1); }
                *reinterpret_cast<float2*>(Cout + (size_t)row0 * ldCL + col) =
                    make_float2(v0, v1);
            }
            if (row0 + 8 < M) {
                float v2 = acc[i][j][2] + bx;
                float v3 = acc[i][j][3] + by;
                s0 += v2; q0 = fmaf(v2, v2, q0);
                s1 += v3; q1 = fmaf(v3, v3, q1);
                if (doRound) { v2 = roundtf(v2); v3 = roundtf(v3); }
                *reinterpret_cast<float2*>(Cout + (size_t)(row0 + 8) * ldCL + col) =
                    make_float2(v2, v3);
            }
        }
        if (stats) {
#pragma unroll
            for (int o = 4; o <= 16; o <<= 1) {
                s0 += __shfl_xor_sync(0xffffffffu, s0, o);
                s1 += __shfl_xor_sync(0xffffffffu, s1, o);
                q0 += __shfl_xor_sync(0xffffffffu, q0, o);
                q1 += __shfl_xor_sync(0xffffffffu, q1, o);
            }
            if (g == 0) {
                atomicAdd(&statsBase[col],           s0);
                atomicAdd(&statsBase[col + 1],       s1);
                atomicAdd(&statsBase[DIM + col],     q0);
                atomicAdd(&statsBase[DIM + col + 1], q1);
            }
        }
    }
}

// ---------------------------------------------------------------------------
// Combined 3-layer CSR build + stats zero
// ---------------------------------------------------------------------------
__global__ void zero_all_kernel(int* __restrict__ deg, float* __restrict__ stats) {
    int i = blockIdx.x * blockDim.x + threadIdx.x;
    if (i < NTOT) deg[i] = 0;
    if (i < 3 * 2 * DIM) stats[i] = 0.f;
}

__global__ void count3_kernel(const int* __restrict__ ei1, const int* __restrict__ ei2,
                              const int* __restrict__ ei3, int E1, int E2, int E3,
                              int* __restrict__ deg) {
    int i = blockIdx.x * blockDim.x + threadIdx.x;
    const int* dst; int idx, off;
    if (i < E1)                { dst = ei1 + E1; idx = i;            off = 0; }
    else if (i < E1 + E2)      { dst = ei2 + E2; idx = i - E1;       off = NN1; }
    else if (i < E1 + E2 + E3) { dst = ei3 + E3; idx = i - E1 - E2;  off = NN1 + NN2; }
    else return;
    atomicAdd(&deg[off + dst[idx]], 1);
}

__global__ void scan3_kernel(const int* __restrict__ deg, int* __restrict__ start,
                             int* __restrict__ cursor) {
    __shared__ int sh[1024];
    __shared__ int carry;
    int t = threadIdx.x;
    const int Ms[3]     = {NN1, NN2, NN3};
    const int degoff[3] = {0, NN1, NN1 + NN2};
    const int stoff[3]  = {0, NN1 + 1, NN1 + NN2 + 2};
    for (int seg = 0; seg < 3; seg++) {
        int M = Ms[seg];
        if (t == 0) carry = 0;
        __syncthreads();
        for (int base = 0; base < M; base += 1024) {
            int i = base + t;
            int v = (i < M) ? deg[degoff[seg] + i] : 0;
            sh[t] = v;
            __syncthreads();
            for (int off = 1; off < 1024; off <<= 1) {
                int u = (t >= off) ? sh[t - off] : 0;
                __syncthreads();
                sh[t] += u;
                __syncthreads();
            }
            if (i < M) {
                start[stoff[seg] + i] = carry + sh[t] - v;
                cursor[degoff[seg] + i] = 0;
            }
            __syncthreads();
            if (t == 1023) carry += sh[1023];
            __syncthreads();
        }
        if (t == 0) start[stoff[seg] + M] = carry;
        __syncthreads();
    }
}

__global__ void fill3_kernel(const int* __restrict__ ei1, const int* __restrict__ ei2,
                             const int* __restrict__ ei3, int E1, int E2, int E3,
                             const int* __restrict__ start, int* __restrict__ cursor,
                             int* __restrict__ adj) {
    int i = blockIdx.x * blockDim.x + threadIdx.x;
    const int* src; const int* dst; int idx, noff, soff, aoff;
    if (i < E1)                { src = ei1; dst = ei1 + E1; idx = i;           noff = 0;         soff = 0;             aoff = 0; }
    else if (i < E1 + E2)      { src = ei2; dst = ei2 + E2; idx = i - E1;      noff = NN1;       soff = NN1 + 1;       aoff = E1; }
    else if (i < E1 + E2 + E3) { src = ei3; dst = ei3 + E3; idx = i - E1 - E2; noff = NN1 + NN2; soff = NN1 + NN2 + 2; aoff = E1 + E2; }
    else return;
    int d = dst[idx];
    int p = atomicAdd(&cursor[noff + d], 1);
    adj[aoff + start[soff + d] + p] = src[idx];
}

// one block (128 threads) per dst row: mean of gathered neighbor rows,
// output rounded to tf32 (RNA). (round-11 form)
__global__ void gather_mean_kernel(const float* __restrict__ x,
                                   const int* __restrict__ adj,
                                   const int* __restrict__ start,
                                   float* __restrict__ mean, int M) {
    int d = blockIdx.x;
    if (d >= M) return;
    int t = threadIdx.x;
    int s0 = start[d], s1 = start[d + 1];
    float4 a0 = make_float4(0.f, 0.f, 0.f, 0.f);
    float4 a1 = make_float4(0.f, 0.f, 0.f, 0.f);
    float4 a2 = make_float4(0.f, 0.f, 0.f, 0.f);
    float4 a3 = make_float4(0.f, 0.f, 0.f, 0.f);
    int j = s0;
    for (; j + 4 <= s1; j += 4) {
        int nA = adj[j], nB = adj[j + 1], nC = adj[j + 2], nD = adj[j + 3];
        float4 vA = reinterpret_cast<const float4*>(x + (size_t)nA * DIM)[t];
        float4 vB = reinterpret_cast<const float4*>(x + (size_t)nB * DIM)[t];
        float4 vC = reinterpret_cast<const float4*>(x + (size_t)nC * DIM)[t];
        float4 vD = reinterpret_cast<const float4*>(x + (size_t)nD * DIM)[t];
        a0.x += vA.x; a0.y += vA.y; a0.z += vA.z; a0.w += vA.w;
        a1.x += vB.x; a1.y += vB.y; a1.z += vB.z; a1.w += vB.w;
        a2.x += vC.x; a2.y += vC.y; a2.z += vC.z; a2.w += vC.w;
        a3.x += vD.x; a3.y += vD.y; a3.z += vD.z; a3.w += vD.w;
    }
    for (; j < s1; j++) {
        int nA = adj[j];
        float4 vA = reinterpret_cast<const float4*>(x + (size_t)nA * DIM)[t];
        a0.x += vA.x; a0.y += vA.y; a0.z += vA.z; a0.w += vA.w;
    }
    int deg = s1 - s0;
    float inv = 1.f / (float)(deg > 1 ? deg : 1);
    float4 r;
    r.x = roundtf(((a0.x + a1.x) + (a2.x + a3.x)) * inv);
    r.y = roundtf(((a0.y + a1.y) + (a2.y + a3.y)) * inv);
    r.z = roundtf(((a0.z + a1.z) + (a2.z + a3.z)) * inv);
    r.w = roundtf(((a0.w + a1.w) + (a2.w + a3.w)) * inv);
    reinterpret_cast<float4*>(mean + (size_t)d * DIM)[t] = r;
}

// ---------------------------------------------------------------------------
// Weight transpose (output rounded to tf32 RNA): [K,N] -> [N,K]
// ---------------------------------------------------------------------------
struct TPtrs { const float* in[7]; float* out[7]; };

__global__ void transpose7_kernel(TPtrs p) {
    __shared__ float t[32][33];
    const float* in = p.in[blockIdx.z];
    float* out = p.out[blockIdx.z];
    int kb = blockIdx.y * 32, nb = blockIdx.x * 32;
    int tx = threadIdx.x, ty = threadIdx.y;
#pragma unroll
    for (int i = 0; i < 32; i += 8)
        t[ty + i][tx] = in[(size_t)(kb + ty + i) * 512 + nb + tx];
    __syncthreads();
#pragma unroll
    for (int i = 0; i < 32; i += 8)
        out[(size_t)(nb + ty + i) * 512 + kb + tx] = roundtf(t[tx][ty + i]);
}

__global__ void transpose_kernel(const float* __restrict__ in, float* __restrict__ out,
                                 int K, int N) {
    __shared__ float t[32][33];
    int kb = blockIdx.y * 32, nb = blockIdx.x * 32;
    int tx = threadIdx.x, ty = threadIdx.y;
#pragma unroll
    for (int i = 0; i < 32; i += 8)
        t[ty + i][tx] = in[(size_t)(kb + ty + i) * N + nb + tx];
    __syncthreads();
#pragma unroll
    for (int i = 0; i < 32; i += 8)
        out[(size_t)(nb + ty + i) * K + kb + tx] = roundtf(t[tx][ty + i]);
}

// rounded copy: x -> xr (tf32 RNA)
__global__ void round_copy_kernel(const float* __restrict__ in, float* __restrict__ out, int n4) {
    int i = blockIdx.x * blockDim.x + threadIdx.x;
    if (i < n4) {
        float4 v = reinterpret_cast<const float4*>(in)[i];
        v.x = roundtf(v.x); v.y = roundtf(v.y); v.z = roundtf(v.z); v.w = roundtf(v.w);
        reinterpret_cast<float4*>(out)[i] = v;
    }
}

// ---------------------------------------------------------------------------
// BN / misc (round-11 forms)
// ---------------------------------------------------------------------------
__global__ void finalize_kernel(int M, const float* __restrict__ g,
                                const float* __restrict__ b,
                                const float* __restrict__ statsBase) {
    int f = threadIdx.x;
    float inv_m = 1.f / (float)M;
    float mu  = statsBase[f] * inv_m;
    float var = statsBase[DIM + f] * inv_m - mu * mu;
    float rstd = rsqrtf(var + EPS);
    float a = g[f] * rstd;
    g_ab[f] = a;
    g_ab[DIM + f] = b[f] - mu * a;
}

// x_out = round_tf32(leaky(bn(h)) + res)
__global__ void epilogue_kernel(const float* __restrict__ h, const float* __restrict__ res,
                                float* __restrict__ xout, int M) {
    int i = blockIdx.x * blockDim.x + threadIdx.x;
    if (i < M * (DIM / 4)) {
        int f4 = (i & 127) * 4;
        float4 hv = reinterpret_cast<const float4*>(h)[i];
        float4 rv = reinterpret_cast<const float4*>(res)[i];
        float4 o;
        float v;
        v = fmaf(hv.x, g_ab[f4 + 0], g_ab[DIM + f4 + 0]); v = v > 0.f ? v : 0.01f * v; o.x = roundtf(v + rv.x);
        v = fmaf(hv.y, g_ab[f4 + 1], g_ab[DIM + f4 + 1]); v = v > 0.f ? v : 0.01f * v; o.y = roundtf(v + rv.y);
        v = fmaf(hv.z, g_ab[f4 + 2], g_ab[DIM + f4 + 2]); v = v > 0.f ? v : 0.01f * v; o.z = roundtf(v + rv.z);
        v = fmaf(hv.w, g_ab[f4 + 3], g_ab[DIM + f4 + 3]); v = v > 0.f ? v : 0.01f * v; o.w = roundtf(v + rv.w);
        reinterpret_cast<float4*>(xout)[i] = o;
    }
}

__global__ void lsm_kernel(const float* __restrict__ z, float* __restrict__ out) {
    int row = blockIdx.x;
    int t = threadIdx.x;
    float v = z[(size_t)row * OUTD + t];
    __shared__ float sh[8];
    float m = v;
#pragma unroll
    for (int o = 16; o; o >>= 1) m = fmaxf(m, __shfl_xor_sync(0xffffffffu, m, o));
    if ((t & 31) == 0) sh[t >> 5] = m;
    __syncthreads();
    if (t == 0) {
        float mm = sh[0];
#pragma unroll
        for (int i = 1; i < 8; i++) mm = fmaxf(mm, sh[i]);
        sh[0] = mm;
    }
    __syncthreads();
    float mx = sh[0];
    __syncthreads();
    float e = expf(v - mx);
    float s = e;
#pragma unroll
    for (int o = 16; o; o >>= 1) s += __shfl_xor_sync(0xffffffffu, s, o);
    if ((t & 31) == 0) sh[t >> 5] = s;
    __syncthreads();
    if (t == 0) {
        float ss = 0.f;
#pragma unroll
        for (int i = 0; i < 8; i++) ss += sh[i];
        sh[0] = ss;
    }
    __syncthreads();
    out[(size_t)row * OUTD + t] = v - mx - logf(sh[0]);
}

// ---------------------------------------------------------------------------
// Host orchestration
// ---------------------------------------------------------------------------
static inline int ceil_div(int a, int b) { return (a + b - 1) / b; }

extern "C" void kernel_launch(void* const* d_in, const int* in_sizes, int n_in,
                              void* d_out, int out_size) {
    const float* x      = (const float*)d_in[0];
    const int*   ei1    = (const int*)  d_in[1];
    const int*   ei2    = (const int*)  d_in[2];
    const int*   ei3    = (const int*)  d_in[3];
    const float* Wl1    = (const float*)d_in[4];
    const float* Wr1    = (const float*)d_in[5];
    const float* g1     = (const float*)d_in[6];
    const float* b1     = (const float*)d_in[7];
    const float* Wl2    = (const float*)d_in[8];
    const float* Wr2    = (const float*)d_in[9];
    const float* g2     = (const float*)d_in[10];
    const float* b2     = (const float*)d_in[11];
    const float* Wl3    = (const float*)d_in[12];
    const float* Wr3    = (const float*)d_in[13];
    const float* g3     = (const float*)d_in[14];
    const float* b3     = (const float*)d_in[15];
    const float* res_W  = (const float*)d_in[16];
    const float* res_b  = (const float*)d_in[17];
    const float* mlp_W1 = (const float*)d_in[18];
    const float* mlp_b1 = (const float*)d_in[19];
    const float* mlp_W2 = (const float*)d_in[20];
    const float* mlp_b2 = (const float*)d_in[21];
    float* out = (float*)d_out;

    int E1 = in_sizes[1] / 2;
    int E2 = in_sizes[2] / 2;
    int E3 = in_sizes[3] / 2;
    int ET = E1 + E2 + E3;

    cudaFuncSetAttribute(fused_gemm_kernel,
                         cudaFuncAttributeMaxDynamicSharedMemorySize, GEMM_SMEM);

    float *p_mean, *p_h, *p_r, *p_xr, *p_x1, *p_x2, *p_x3, *p_z1, *p_z2, *p_stats, *p_wt;
    int *p_deg, *p_start, *p_cur, *p_adj;
    cudaGetSymbolAddress((void**)&p_mean,  g_mean);
    cudaGetSymbolAddress((void**)&p_h,     g_h);
    cudaGetSymbolAddress((void**)&p_r,     g_r);
    cudaGetSymbolAddress((void**)&p_xr,    g_xr);
    cudaGetSymbolAddress((void**)&p_x1,    g_x1);
    cudaGetSymbolAddress((void**)&p_x2,    g_x2);
    cudaGetSymbolAddress((void**)&p_x3,    g_x3);
    cudaGetSymbolAddress((void**)&p_z1,    g_z1);
    cudaGetSymbolAddress((void**)&p_z2,    g_z2);
    cudaGetSymbolAddress((void**)&p_stats, g_stats);
    cudaGetSymbolAddress((void**)&p_wt,    g_wt);
    cudaGetSymbolAddress((void**)&p_deg,   g_deg);
    cudaGetSymbolAddress((void**)&p_start, g_start);
    cudaGetSymbolAddress((void**)&p_cur,   g_cur);
    cudaGetSymbolAddress((void**)&p_adj,   g_adj);

    // --- combined CSR build + stats zero ---
    zero_all_kernel<<<ceil_div(NTOT, 256), 256>>>(p_deg, p_stats);
    count3_kernel<<<ceil_div(ET, 256), 256>>>(ei1, ei2, ei3, E1, E2, E3, p_deg);
    scan3_kernel<<<1, 1024>>>(p_deg, p_start, p_cur);
    fill3_kernel<<<ceil_div(ET, 256), 256>>>(ei1, ei2, ei3, E1, E2, E3,
                                             p_start, p_cur, p_adj);

    // --- transpose all weights to K-major [N, K], rounded to tf32 ---
    float* wt_Wl1 = p_wt + 0 * WT_SEG;
    float* wt_Wr1 = p_wt + 1 * WT_SEG;
    float* wt_Wl2 = p_wt + 2 * WT_SEG;
    float* wt_Wr2 = p_wt + 3 * WT_SEG;
    float* wt_Wl3 = p_wt + 4 * WT_SEG;
    float* wt_Wr3 = p_wt + 5 * WT_SEG;
    float* wt_res = p_wt + 6 * WT_SEG;
    float* wt_W1  = p_wt + WT_W1;
    float* wt_W2  = p_wt + WT_W2;
    {
        dim3 blk(32, 8);
        TPtrs tp;
        tp.in[0] = Wl1;  tp.out[0] = wt_Wl1;
        tp.in[1] = Wr1;  tp.out[1] = wt_Wr1;
        tp.in[2] = Wl2;  tp.out[2] = wt_Wl2;
        tp.in[3] = Wr2;  tp.out[3] = wt_Wr2;
        tp.in[4] = Wl3;  tp.out[4] = wt_Wl3;
        tp.in[5] = Wr3;  tp.out[5] = wt_Wr3;
        tp.in[6] = res_W; tp.out[6] = wt_res;
        transpose7_kernel<<<dim3(16, 16, 7), blk>>>(tp);
        transpose_kernel<<<dim3(16, 64), blk>>>(mlp_W1, wt_W1, 2048, 512);
        transpose_kernel<<<dim3(8,  16), blk>>>(mlp_W2, wt_W2, 512, 256);
    }

    // rounded copy of x rows 0..NN1 (GEMM A operand for layer 1 + MLP)
    round_copy_kernel<<<ceil_div(NN1 * (DIM / 4), 256), 256>>>(x, p_xr, NN1 * (DIM / 4));

    struct Layer {
        int M;
        const float* x_gather;
        const float* x_gemm;
        const int* startL; const int* adjL;
        const float* Wlt; const float* Wrt; const float* g; const float* b;
        float* x_out;
    };
    Layer layers[3] = {
        { NN1, x,    p_xr, p_start,                 p_adj,           wt_Wl1, wt_Wr1, g1, b1, p_x1 },
        { NN2, p_x1, p_x1, p_start + NN1 + 1,       p_adj + E1,      wt_Wl2, wt_Wr2, g2, b2, p_x2 },
        { NN3, p_x2, p_x2, p_start + NN1 + NN2 + 2, p_adj + E1 + E2, wt_Wl3, wt_Wr3, g3, b3, p_x3 },
    };

    for (int L = 0; L < 3; L++) {
        Layer& ly = layers[L];
        int M = ly.M;
        float* statsL = p_stats + L * 2 * DIM;

        gather_mean_kernel<<<M, 128>>>(ly.x_gather, ly.adjL, ly.startL, p_mean, M);

        // h = mean @ Wl + x_dst @ Wr (stats fused); L0 also r = x @ res_W + res_b
        {
            int mainX = DIM / 128;
            int altX  = (L == 0) ? (DIM / 128) : 0;
            dim3 grid(mainX + altX, ceil_div(M, 128));
            fused_gemm_kernel<<<grid, 256, GEMM_SMEM>>>(
                p_mean, ly.x_gemm, nullptr, nullptr,
                ly.Wlt, ly.Wrt, nullptr, nullptr,
                2, 512, nullptr, p_h, DIM,
                M, mainX, 1, statsL, 0,
                (L == 0) ? ly.x_gemm : nullptr,
                (L == 0) ? wt_res : nullptr,
                (L == 0) ? res_b : nullptr,
                (L == 0) ? p_r : nullptr);
        }

        finalize_kernel<<<1, DIM>>>(M, ly.g, ly.b, statsL);

        const float* res = (L == 0) ? p_r : ly.x_gemm;
        epilogue_kernel<<<ceil_div(M * (DIM / 4), 256), 256>>>(p_h, res, ly.x_out, M);
    }

    // MLP head: feat = [x | x1 | x2 | x3][:8000] (implicit concat); round z1
    {
        dim3 grid(DIM / 128, ceil_div(NN3, 128));
        fused_gemm_kernel<<<grid, 256, GEMM_SMEM>>>(
            p_xr, p_x1, p_x2, p_x3,
            wt_W1, wt_W1 + 512, wt_W1 + 1024, wt_W1 + 1536,
            4, 2048, mlp_b1, p_z1, DIM,
            NN3, DIM / 128, 0, nullptr, 1,
            nullptr, nullptr, nullptr, nullptr);
    }
    {
        dim3 grid(OUTD / 128, ceil_div(NN3, 128));
        fused_gemm_kernel<<<grid, 256, GEMM_SMEM>>>(
            p_z1, nullptr, nullptr, nullptr,
            wt_W2, nullptr, nullptr, nullptr,
            1, 512, mlp_b2, p_z2, OUTD,
            NN3, OUTD / 128, 0, nullptr, 0,
            nullptr, nullptr, nullptr, nullptr);
    }

    lsm_kernel<<<NN3, OUTD>>>(p_z2, out);
}